// round 9
// baseline (speedup 1.0000x reference)
#include <cuda_runtime.h>
#include <cstddef>

// PCEN: out = (x / (FLOOR + ema(x))^alpha + delta)^(1/root) - delta^(1/root)
// ema: m_t = s*x_t + (1-s)*m_{t-1}, m_0 = x_0, s = 0.025.
//
// R9: load-balance fix on top of R8. Non-uniform chunks so every warp does
// exactly 46 tiles: chunk 0 emits 736 rows (no halo), chunks 1..7 emit 480
// rows after a 256-row halo burn-in (736 + 7*480 = 4096). 64-thread blocks
// (2 warps) shrink the per-SM block-count quantization to ~1%.
// Pipeline unchanged: static double-buffered 16-row tiles, float1, stcs.

namespace {
constexpr int   Bn = 64, Tn = 4096, Cn = 128;
constexpr float S_COEF = 0.025f;
constexpr float INV_S  = 40.0f;           // 1/s
constexpr float OMS    = 0.975f;
constexpr float FLOORV = 1e-6f;
constexpr int   NC      = 8;              // chunks along T
constexpr int   CHUNK0  = 736;            // chunk 0 emit rows (no halo)
constexpr int   CHUNKR  = 480;            // chunks 1..7 emit rows
constexpr int   HALO    = 256;            // burn-in rows (decay ~1.5e-3)
constexpr int   U       = 16;             // rows per tile
constexpr int   NTILES  = 46;             // tiles per warp (uniform!)
constexpr int   THREADS = 64;             // 2 warps/block
constexpr int   NWARPS  = Bn * NC * 4;    // 2048 warps
constexpr int   NBLOCKS = NWARPS * 32 / THREADS;  // 1024
static_assert(CHUNK0 + 7 * CHUNKR == Tn, "partition must cover T");
static_assert(CHUNK0 / U == NTILES, "chunk0 tiles");
static_assert((HALO + CHUNKR) / U == NTILES, "rest tiles");
static_assert(NTILES % 2 == 0, "double-buffer loop needs even tile count");
}

__device__ __forceinline__ float f_lg2(float x) {
    float r; asm("lg2.approx.f32 %0, %1;" : "=f"(r) : "f"(x)); return r;
}
__device__ __forceinline__ float f_ex2(float x) {
    float r; asm("ex2.approx.f32 %0, %1;" : "=f"(r) : "f"(x)); return r;
}
__device__ __forceinline__ float f_sqt(float x) {
    float r; asm("sqrt.approx.f32 %0, %1;" : "=f"(r) : "f"(x)); return r;
}

// Pointwise PCEN. mp = m/S (scaled EMA state). SQ = (1/root == 0.5) fast path.
template <bool SQ>
__device__ __forceinline__ float pcen_pt(float xv, float mp, float na, float d,
                                         float ri, float t3) {
    float mm     = fmaf(S_COEF, mp, FLOORV);       // FLOOR + m (off the chain)
    float inv_t1 = f_ex2(na * f_lg2(mm));          // (FLOOR+m)^(-alpha)
    float y      = fmaf(xv, inv_t1, d);            // x/term1 + delta
    float t2     = SQ ? f_sqt(y) : f_ex2(ri * f_lg2(y));
    return t2 - t3;
}

// Consume one U-row tile held in registers. emit is warp-uniform.
template <bool SQ>
__device__ __forceinline__ void consume_tile(const float* __restrict__ xs,
                                             bool emit, float* __restrict__ po,
                                             int emit_off, float& m,
                                             float na, float d, float ri,
                                             float t3) {
    if (emit) {
        float* pot = po + (size_t)emit_off * Cn;
        #pragma unroll
        for (int i = 0; i < U; ++i) {
            m = fmaf(OMS, m, xs[i]);               // 4-cyc dependent chain
            __stcs(pot + i * Cn, pcen_pt<SQ>(xs[i], m, na, d, ri, t3));
        }
    } else {
        #pragma unroll
        for (int i = 0; i < U; ++i) m = fmaf(OMS, m, xs[i]);
    }
}

template <bool SQ>
__device__ __forceinline__ void run_seq(const float* __restrict__ p,
                                        float* __restrict__ po, int NH,
                                        float na, float d, float ri, float t3) {
    // scaled EMA state m' = m/S. Init m' = 40*x0 so consuming row 0 of tile 0
    // yields m = x[tstart] (exact for chunk 0 through the normal emit path).
    float m = INV_S * p[0];

    float bufA[U], bufB[U];
    #pragma unroll
    for (int i = 0; i < U; ++i) bufA[i] = p[i * Cn];        // preload tile 0

    // NTILES even: tile t+1 always exists inside the loop.
    for (int t = 0; t < NTILES; t += 2) {
        const float* p1 = p + (size_t)(t + 1) * U * Cn;
        #pragma unroll
        for (int i = 0; i < U; ++i) bufB[i] = p1[i * Cn];   // prefetch t+1

        consume_tile<SQ>(bufA, t >= NH, po, (t - NH) * U, m, na, d, ri, t3);

        if (t + 2 < NTILES) {
            const float* p2 = p + (size_t)(t + 2) * U * Cn;
            #pragma unroll
            for (int i = 0; i < U; ++i) bufA[i] = p2[i * Cn];  // prefetch t+2
        }

        consume_tile<SQ>(bufB, t + 1 >= NH, po, (t + 1 - NH) * U, m, na, d, ri, t3);
    }
}

__global__ void __launch_bounds__(THREADS, 1)
pcen_kernel(const float* __restrict__ x,
            const float* __restrict__ alpha,
            const float* __restrict__ delta,
            const float* __restrict__ root,
            float* __restrict__ out) {
    int gtid = blockIdx.x * blockDim.x + threadIdx.x;
    int w    = gtid >> 5;
    int lane = threadIdx.x & 31;

    // warp -> (b, chunk, quarter); 32 warps per batch; thread -> 1 channel
    int b       = w >> 5;
    int r       = w & 31;
    int chunk   = r >> 2;
    int quarter = r & 3;
    int c       = quarter * 32 + lane;

    // per-channel constants
    float a  = fminf(alpha[c], 1.0f);
    float d  = delta[c];
    float ri = 1.0f / fmaxf(root[c], 1.0f);
    float na = -a;
    bool  sq = (ri == 0.5f);
    // term3 via the SAME approx path as term2 so the x->0 limit cancels exactly
    float t3 = sq ? f_sqt(d) : f_ex2(ri * f_lg2(d));

    // non-uniform partition: every warp walks exactly NTILES tiles
    int t0     = (chunk == 0) ? 0 : (CHUNK0 + (chunk - 1) * CHUNKR);
    int tstart = (chunk == 0) ? 0 : (t0 - HALO);
    int NH     = (chunk == 0) ? 0 : (HALO / U);   // 0 or 16

    const float* px = x   + ((size_t)b * Tn + tstart) * Cn + c;
    float*       po = out + ((size_t)b * Tn + t0)     * Cn + c;

    if (sq) run_seq<true >(px, po, NH, na, d, ri, t3);
    else    run_seq<false>(px, po, NH, na, d, ri, t3);
}

extern "C" void kernel_launch(void* const* d_in, const int* in_sizes, int n_in,
                              void* d_out, int out_size) {
    const float* x     = (const float*)d_in[0];
    const float* alpha = (const float*)d_in[1];
    const float* delta = (const float*)d_in[2];
    const float* root  = (const float*)d_in[3];
    float*       out   = (float*)d_out;
    (void)in_sizes; (void)n_in; (void)out_size;

    pcen_kernel<<<NBLOCKS, THREADS>>>(x, alpha, delta, root, out);
}

// round 10
// speedup vs baseline: 1.0365x; 1.0365x over previous
#include <cuda_runtime.h>
#include <cstddef>

// PCEN: out = (x / (FLOOR + ema(x))^alpha + delta)^(1/root) - delta^(1/root)
// ema: m_t = s*x_t + (1-s)*m_{t-1}, m_0 = x_0, s = 0.025.
//
// R10: R8 (NC=8, CHUNK=512, HALO=256, float1, 4 warps/(b,chunk), stcs,
// launch_bounds(...,1)) with U=32: 32 batched loads then 32 stores per tile.
// Doubles per-warp MLP (32 LDGs in flight) and doubles same-direction DRAM
// burst length to cut read<->write turnaround overhead at the HBM.

namespace {
constexpr int   Bn = 64, Tn = 4096, Cn = 128;
constexpr float S_COEF = 0.025f;
constexpr float INV_S  = 40.0f;           // 1/s
constexpr float OMS    = 0.975f;
constexpr float FLOORV = 1e-6f;
constexpr int   NC     = 8;               // chunks along T
constexpr int   CHUNK  = Tn / NC;         // 512
constexpr int   HALO   = 256;             // burn-in rows (decay ~1.5e-3)
constexpr int   U      = 32;              // rows per tile (MLP / burst length)
constexpr int   THREADS = 64;             // 2 warps/block
constexpr int   NWARPS  = Bn * NC * 4;    // 2048 warps
constexpr int   NBLOCKS = NWARPS * 32 / THREADS;  // 1024
static_assert(CHUNK % U == 0 && HALO % U == 0, "tiles must divide regions");
static_assert((CHUNK / U) % 2 == 0 && ((CHUNK + HALO) / U) % 2 == 0,
              "double-buffer loop needs even tile count");
}

__device__ __forceinline__ float f_lg2(float x) {
    float r; asm("lg2.approx.f32 %0, %1;" : "=f"(r) : "f"(x)); return r;
}
__device__ __forceinline__ float f_ex2(float x) {
    float r; asm("ex2.approx.f32 %0, %1;" : "=f"(r) : "f"(x)); return r;
}
__device__ __forceinline__ float f_sqt(float x) {
    float r; asm("sqrt.approx.f32 %0, %1;" : "=f"(r) : "f"(x)); return r;
}

// Pointwise PCEN. mp = m/S (scaled EMA state). SQ = (1/root == 0.5) fast path.
template <bool SQ>
__device__ __forceinline__ float pcen_pt(float xv, float mp, float na, float d,
                                         float ri, float t3) {
    float mm     = fmaf(S_COEF, mp, FLOORV);       // FLOOR + m (off the chain)
    float inv_t1 = f_ex2(na * f_lg2(mm));          // (FLOOR+m)^(-alpha)
    float y      = fmaf(xv, inv_t1, d);            // x/term1 + delta
    float t2     = SQ ? f_sqt(y) : f_ex2(ri * f_lg2(y));
    return t2 - t3;
}

// Consume one U-row tile held in registers. emit is warp-uniform.
template <bool SQ>
__device__ __forceinline__ void consume_tile(const float* __restrict__ xs,
                                             bool emit, float* __restrict__ po,
                                             int emit_off, float& m,
                                             float na, float d, float ri,
                                             float t3) {
    if (emit) {
        float* pot = po + (size_t)emit_off * Cn;
        #pragma unroll
        for (int i = 0; i < U; ++i) {
            m = fmaf(OMS, m, xs[i]);               // 4-cyc dependent chain
            __stcs(pot + i * Cn, pcen_pt<SQ>(xs[i], m, na, d, ri, t3));
        }
    } else {
        #pragma unroll
        for (int i = 0; i < U; ++i) m = fmaf(OMS, m, xs[i]);
    }
}

template <bool SQ>
__device__ __forceinline__ void run_seq(const float* __restrict__ p,
                                        float* __restrict__ po,
                                        int NH, int NT,
                                        float na, float d, float ri, float t3) {
    // scaled EMA state m' = m/S. Init m' = 40*x0 so consuming row 0 of tile 0
    // yields m = x[tstart] (exact for chunk 0 through the normal emit path).
    float m = INV_S * p[0];

    float bufA[U], bufB[U];
    #pragma unroll
    for (int i = 0; i < U; ++i) bufA[i] = p[i * Cn];        // preload tile 0

    // NT is even (16 or 24): tile t+1 always exists inside the loop.
    for (int t = 0; t < NT; t += 2) {
        const float* p1 = p + (size_t)(t + 1) * U * Cn;
        #pragma unroll
        for (int i = 0; i < U; ++i) bufB[i] = p1[i * Cn];   // prefetch t+1

        consume_tile<SQ>(bufA, t >= NH, po, (t - NH) * U, m, na, d, ri, t3);

        if (t + 2 < NT) {
            const float* p2 = p + (size_t)(t + 2) * U * Cn;
            #pragma unroll
            for (int i = 0; i < U; ++i) bufA[i] = p2[i * Cn];  // prefetch t+2
        }

        consume_tile<SQ>(bufB, t + 1 >= NH, po, (t + 1 - NH) * U, m, na, d, ri, t3);
    }
}

__global__ void __launch_bounds__(THREADS, 1)
pcen_kernel(const float* __restrict__ x,
            const float* __restrict__ alpha,
            const float* __restrict__ delta,
            const float* __restrict__ root,
            float* __restrict__ out) {
    int gtid = blockIdx.x * blockDim.x + threadIdx.x;
    int w    = gtid >> 5;
    int lane = threadIdx.x & 31;

    // warp -> (b, chunk, quarter); 32 warps per batch; thread -> 1 channel
    int b       = w >> 5;
    int r       = w & 31;
    int chunk   = r >> 2;
    int quarter = r & 3;
    int c       = quarter * 32 + lane;

    // per-channel constants
    float a  = fminf(alpha[c], 1.0f);
    float d  = delta[c];
    float ri = 1.0f / fmaxf(root[c], 1.0f);
    float na = -a;
    bool  sq = (ri == 0.5f);
    // term3 via the SAME approx path as term2 so the x->0 limit cancels exactly
    float t3 = sq ? f_sqt(d) : f_ex2(ri * f_lg2(d));

    int t0     = chunk * CHUNK;
    int tstart = (chunk == 0) ? 0 : (t0 - HALO);
    int NH     = (t0 - tstart) / U;          // 0 (chunk 0) or 8
    int NT     = NH + CHUNK / U;             // 16 or 24 (always even)

    const float* px = x   + ((size_t)b * Tn + tstart) * Cn + c;
    float*       po = out + ((size_t)b * Tn + t0)     * Cn + c;

    if (sq) run_seq<true >(px, po, NH, NT, na, d, ri, t3);
    else    run_seq<false>(px, po, NH, NT, na, d, ri, t3);
}

extern "C" void kernel_launch(void* const* d_in, const int* in_sizes, int n_in,
                              void* d_out, int out_size) {
    const float* x     = (const float*)d_in[0];
    const float* alpha = (const float*)d_in[1];
    const float* delta = (const float*)d_in[2];
    const float* root  = (const float*)d_in[3];
    float*       out   = (float*)d_out;
    (void)in_sizes; (void)n_in; (void)out_size;

    pcen_kernel<<<NBLOCKS, THREADS>>>(x, alpha, delta, root, out);
}